// round 1
// baseline (speedup 1.0000x reference)
#include <cuda_runtime.h>
#include <cuda_bf16.h>

namespace {
constexpr int TILE = 30;   // output tile edge
constexpr int CORR = 32;   // corr region edge = TILE + 2 (box-filter halo)
constexpr int NS   = 40;   // noise region edge = TILE + 2 + 8 (shift halo)
constexpr int NSTR = 40;   // noise smem row stride (mult of 4 for float4)
constexpr int CSTR = 36;   // corr smem row stride (mult of 4)
constexpr int CH   = 16;
constexpr int H = 192, W = 192;
constexpr int SMEM_BYTES = (CH * NS * NSTR + 9 * CORR * CSTR) * 4; // 143872
}

__global__ __launch_bounds__(256, 1)
void noisecorr_kernel(const float* __restrict__ noise, float* __restrict__ out)
{
    extern __shared__ float smem[];
    float* sN = smem;                    // [16][40][40]
    float* sC = smem + CH * NS * NSTR;   // [9][32][36]

    const int tid = threadIdx.x;
    const int b   = blockIdx.z;
    const int ty0 = blockIdx.y * TILE;
    const int tx0 = blockIdx.x * TILE;

    const float* nb = noise + (size_t)b * CH * H * W;

    // ---- Load 40x40x16 noise halo region (zero padded outside image) ----
    #pragma unroll 4
    for (int idx = tid; idx < CH * NS * NS; idx += 256) {
        int c  = idx / (NS * NS);
        int r  = idx - c * (NS * NS);
        int yy = r / NS;
        int xx = r - yy * NS;
        int gy = ty0 - 5 + yy;
        int gx = tx0 - 5 + xx;
        float v = 0.0f;
        if ((unsigned)gy < (unsigned)H && (unsigned)gx < (unsigned)W)
            v = nb[(c * H + gy) * W + gx];
        sN[(c * NS + yy) * NSTR + xx] = v;
    }
    __syncthreads();

    // corr-point ownership: 32 rows x 8 groups of 4 columns = 1024 pts = 256 thr x 4
    const int ry = tid >> 3;           // corr-local row 0..31
    const int x0 = (tid & 7) << 2;     // corr-local col base 0..28 (4-aligned)

    // ---- Center operand: held in registers across all 81 offsets ----
    // corr-local (ry, x0+j) <-> noise-local (ry+4, x0+4+j)
    float cen[CH][4];
    #pragma unroll
    for (int c = 0; c < CH; c++) {
        float4 v = *(const float4*)&sN[(c * NS + ry + 4) * NSTR + x0 + 4];
        cen[c][0] = v.x; cen[c][1] = v.y; cen[c][2] = v.z; cen[c][3] = v.w;
    }

    const float inv = 1.0f / 144.0f;   // 1 / (C * K * K)
    const bool rowvalid = (ry < TILE) && (ty0 + ry < H);
    const int  oy = ty0 + ry;

    #pragma unroll 1
    for (int di = 0; di < 9; di++) {
        // 4 points x 9 dj accumulators
        float acc[4][9];
        #pragma unroll
        for (int j = 0; j < 4; j++)
            #pragma unroll
            for (int dj = 0; dj < 9; dj++)
                acc[j][dj] = 0.0f;

        // Shifted operand: noise-local row = ry + di, cols x0 .. x0+11
        // loaded as 4 aligned float4 (16 floats), shared across all 9 dj.
        #pragma unroll
        for (int c = 0; c < CH; c++) {
            const float* row = &sN[(c * NS + ry + di) * NSTR + x0];
            float4 a  = *(const float4*)(row + 0);
            float4 bb = *(const float4*)(row + 4);
            float4 cc = *(const float4*)(row + 8);
            float4 dd = *(const float4*)(row + 12);
            float sh[16] = { a.x,  a.y,  a.z,  a.w,
                             bb.x, bb.y, bb.z, bb.w,
                             cc.x, cc.y, cc.z, cc.w,
                             dd.x, dd.y, dd.z, dd.w };
            #pragma unroll
            for (int j = 0; j < 4; j++)
                #pragma unroll
                for (int dj = 0; dj < 9; dj++)
                    acc[j][dj] = fmaf(cen[c][j], sh[j + dj], acc[j][dj]);
        }

        __syncthreads();   // previous di's filter has finished reading sC
        #pragma unroll
        for (int dj = 0; dj < 9; dj++) {
            float4 v = make_float4(acc[0][dj], acc[1][dj], acc[2][dj], acc[3][dj]);
            *(float4*)&sC[(dj * CORR + ry) * CSTR + x0] = v;
        }
        __syncthreads();

        // ---- 3x3 box filter + store: out row = ry, cols x0..x0+3 ----
        if (rowvalid) {
            #pragma unroll
            for (int dj = 0; dj < 9; dj++) {
                const float* cb = &sC[(dj * CORR + ry) * CSTR + x0];
                float4 r0a = *(const float4*)(cb);
                float4 r0b = *(const float4*)(cb + 4);
                float4 r1a = *(const float4*)(cb + CSTR);
                float4 r1b = *(const float4*)(cb + CSTR + 4);
                float4 r2a = *(const float4*)(cb + 2 * CSTR);
                float4 r2b = *(const float4*)(cb + 2 * CSTR + 4);
                float col0 = r0a.x + r1a.x + r2a.x;
                float col1 = r0a.y + r1a.y + r2a.y;
                float col2 = r0a.z + r1a.z + r2a.z;
                float col3 = r0a.w + r1a.w + r2a.w;
                float col4 = r0b.x + r1b.x + r2b.x;
                float col5 = r0b.y + r1b.y + r2b.y;
                float o0 = (col0 + col1 + col2) * inv;
                float o1 = (col1 + col2 + col3) * inv;
                float o2 = (col2 + col3 + col4) * inv;
                float o3 = (col3 + col4 + col5) * inv;
                const int p = di * 9 + dj;
                float* ob = out + (((size_t)b * 81 + p) * H + oy) * W + tx0;
                if (x0 + 0 < TILE && tx0 + x0 + 0 < W) ob[x0 + 0] = o0;
                if (x0 + 1 < TILE && tx0 + x0 + 1 < W) ob[x0 + 1] = o1;
                if (x0 + 2 < TILE && tx0 + x0 + 2 < W) ob[x0 + 2] = o2;
                if (x0 + 3 < TILE && tx0 + x0 + 3 < W) ob[x0 + 3] = o3;
            }
        }
    }
}

extern "C" void kernel_launch(void* const* d_in, const int* in_sizes, int n_in,
                              void* d_out, int out_size)
{
    const float* noise = (const float*)d_in[0];
    float* out = (float*)d_out;
    (void)in_sizes; (void)n_in; (void)out_size;

    cudaFuncSetAttribute(noisecorr_kernel,
                         cudaFuncAttributeMaxDynamicSharedMemorySize, SMEM_BYTES);

    dim3 grid((W + TILE - 1) / TILE, (H + TILE - 1) / TILE, 8);  // 7 x 7 x 8
    noisecorr_kernel<<<grid, 256, SMEM_BYTES>>>(noise, out);
}

// round 2
// speedup vs baseline: 1.0374x; 1.0374x over previous
#include <cuda_runtime.h>
#include <cuda_bf16.h>

namespace {
constexpr int TILE = 30;   // output tile edge
constexpr int CORR = 32;   // corr region edge = TILE + 2 (box-filter halo)
constexpr int NS   = 40;   // noise region edge = TILE + 2 + 8 (shift halo)
constexpr int NSTR = 40;   // noise smem row stride
constexpr int CSTR = 36;   // corr smem row stride
constexpr int CH   = 16;
constexpr int H = 192, W = 192;
constexpr int CPLANE = 9 * CORR * CSTR;              // one half's corr buffer (floats)
constexpr int SMEM_BYTES = (CH * NS * NSTR + 2 * CPLANE) * 4;   // 185,344 B
}

__global__ __launch_bounds__(512, 1)
void noisecorr_kernel(const float* __restrict__ noise, float* __restrict__ out)
{
    extern __shared__ float smem[];
    float* sN = smem;                    // [16][40][40]

    const int tid  = threadIdx.x;
    const int half = tid >> 8;           // 0: di 0..4, 1: di 5..8
    const int t    = tid & 255;
    float* sC = smem + CH * NS * NSTR + half * CPLANE;   // [9][32][36] per half

    const int b   = blockIdx.z;
    const int ty0 = blockIdx.y * TILE;
    const int tx0 = blockIdx.x * TILE;

    const float* nb = noise + (size_t)b * CH * H * W;

    // ---- Load 40x40x16 noise halo region (zero padded outside image) ----
    #pragma unroll 4
    for (int idx = tid; idx < CH * NS * NS; idx += 512) {
        int c  = idx / (NS * NS);
        int r  = idx - c * (NS * NS);
        int yy = r / NS;
        int xx = r - yy * NS;
        int gy = ty0 - 5 + yy;
        int gx = tx0 - 5 + xx;
        float v = 0.0f;
        if ((unsigned)gy < (unsigned)H && (unsigned)gx < (unsigned)W)
            v = nb[(c * H + gy) * W + gx];
        sN[(c * NS + yy) * NSTR + xx] = v;
    }
    __syncthreads();

    // corr-point ownership within a half: 32 rows x 8 groups of 4 cols
    const int ry = t >> 3;             // corr-local row 0..31
    const int x0 = (t & 7) << 2;       // corr-local col base 0..28 (4-aligned)

    // ---- Center operand: registers, reused across all this half's offsets ----
    float cen[CH][4];
    #pragma unroll
    for (int c = 0; c < CH; c++) {
        float4 v = *(const float4*)&sN[(c * NS + ry + 4) * NSTR + x0 + 4];
        cen[c][0] = v.x; cen[c][1] = v.y; cen[c][2] = v.z; cen[c][3] = v.w;
    }

    const float inv = 1.0f / 144.0f;   // 1 / (C * K * K)
    const bool rowvalid = (ry < TILE) && (ty0 + ry < H);
    const int  oy = ty0 + ry;

    #pragma unroll 1
    for (int it = 0; it < 5; it++) {
        const int di = half * 5 + it;          // half0: 0..4, half1: 5..9(skip 9)
        const bool active = (di < 9);

        float acc[4][9];
        #pragma unroll
        for (int j = 0; j < 4; j++)
            #pragma unroll
            for (int dj = 0; dj < 9; dj++)
                acc[j][dj] = 0.0f;

        if (active) {
            // Shifted operand: noise-local row ry+di, cols x0 .. x0+11
            // (j + dj spans 0..11 -> 3 aligned float4 loads)
            #pragma unroll
            for (int c = 0; c < CH; c++) {
                const float* row = &sN[(c * NS + ry + di) * NSTR + x0];
                float4 a  = *(const float4*)(row + 0);
                float4 bb = *(const float4*)(row + 4);
                float4 cc = *(const float4*)(row + 8);
                float sh[12] = { a.x,  a.y,  a.z,  a.w,
                                 bb.x, bb.y, bb.z, bb.w,
                                 cc.x, cc.y, cc.z, cc.w };
                #pragma unroll
                for (int j = 0; j < 4; j++)
                    #pragma unroll
                    for (int dj = 0; dj < 9; dj++)
                        acc[j][dj] = fmaf(cen[c][j], sh[j + dj], acc[j][dj]);
            }
        }

        __syncthreads();   // previous iteration's filter done reading sC
        if (active) {
            #pragma unroll
            for (int dj = 0; dj < 9; dj++) {
                float4 v = make_float4(acc[0][dj], acc[1][dj], acc[2][dj], acc[3][dj]);
                *(float4*)&sC[(dj * CORR + ry) * CSTR + x0] = v;
            }
        }
        __syncthreads();

        // ---- 3x3 box filter + store ----
        if (active && rowvalid) {
            #pragma unroll
            for (int dj = 0; dj < 9; dj++) {
                const float* cb = &sC[(dj * CORR + ry) * CSTR + x0];
                float4 r0a = *(const float4*)(cb);
                float4 r0b = *(const float4*)(cb + 4);
                float4 r1a = *(const float4*)(cb + CSTR);
                float4 r1b = *(const float4*)(cb + CSTR + 4);
                float4 r2a = *(const float4*)(cb + 2 * CSTR);
                float4 r2b = *(const float4*)(cb + 2 * CSTR + 4);
                float col0 = r0a.x + r1a.x + r2a.x;
                float col1 = r0a.y + r1a.y + r2a.y;
                float col2 = r0a.z + r1a.z + r2a.z;
                float col3 = r0a.w + r1a.w + r2a.w;
                float col4 = r0b.x + r1b.x + r2b.x;
                float col5 = r0b.y + r1b.y + r2b.y;
                float o0 = (col0 + col1 + col2) * inv;
                float o1 = (col1 + col2 + col3) * inv;
                float o2 = (col2 + col3 + col4) * inv;
                float o3 = (col3 + col4 + col5) * inv;
                const int p = di * 9 + dj;
                float* ob = out + (((size_t)b * 81 + p) * H + oy) * W + tx0;
                if (x0 + 0 < TILE && tx0 + x0 + 0 < W) ob[x0 + 0] = o0;
                if (x0 + 1 < TILE && tx0 + x0 + 1 < W) ob[x0 + 1] = o1;
                if (x0 + 2 < TILE && tx0 + x0 + 2 < W) ob[x0 + 2] = o2;
                if (x0 + 3 < TILE && tx0 + x0 + 3 < W) ob[x0 + 3] = o3;
            }
        }
    }
}

extern "C" void kernel_launch(void* const* d_in, const int* in_sizes, int n_in,
                              void* d_out, int out_size)
{
    const float* noise = (const float*)d_in[0];
    float* out = (float*)d_out;
    (void)in_sizes; (void)n_in; (void)out_size;

    cudaFuncSetAttribute(noisecorr_kernel,
                         cudaFuncAttributeMaxDynamicSharedMemorySize, SMEM_BYTES);

    dim3 grid((W + TILE - 1) / TILE, (H + TILE - 1) / TILE, 8);  // 7 x 7 x 8
    noisecorr_kernel<<<grid, 512, SMEM_BYTES>>>(noise, out);
}

// round 3
// speedup vs baseline: 1.2478x; 1.2028x over previous
#include <cuda_runtime.h>

using ull = unsigned long long;

namespace {
constexpr int TILE = 24;           // output tile edge; 192 % 24 == 0
constexpr int CR   = 26;           // corr rows (TILE + 2)
constexpr int NH   = 34, NW = 36;  // noise region rows/cols (stride NW)
constexpr int HSR  = 28;           // sHS row stride
constexpr int CH   = 16;
constexpr int H = 192, W = 192;
constexpr int SN_FLOATS  = CH * NH * NW;   // 19584
constexpr int SHS_FLOATS = 9 * CR * HSR;   // 6552
constexpr int SMEM_BYTES = (SN_FLOATS + SHS_FLOATS) * 4;  // 104544
constexpr unsigned FULL = 0xffffffffu;
}

__device__ __forceinline__ ull pk(float lo, float hi) {
    ull r; asm("mov.b64 %0, {%1,%2};" : "=l"(r) : "f"(lo), "f"(hi)); return r;
}
__device__ __forceinline__ void upk(ull v, float& lo, float& hi) {
    asm("mov.b64 {%0,%1}, %2;" : "=f"(lo), "=f"(hi) : "l"(v));
}
__device__ __forceinline__ void ffma2(ull& acc, ull m, ull s) {
    asm("fma.rn.f32x2 %0, %1, %2, %0;" : "+l"(acc) : "l"(m), "l"(s));
}

__global__ __launch_bounds__(256, 2)
void noisecorr_kernel(const float* __restrict__ noise, float* __restrict__ out)
{
    extern __shared__ float smem[];
    float* sN  = smem;               // [16][34][36]
    float* sHS = smem + SN_FLOATS;   // [9][26][28]

    const int t   = threadIdx.x;
    const int b   = blockIdx.z;
    const int ty0 = blockIdx.y * TILE;
    const int tx0 = blockIdx.x * TILE;
    const float* nb = noise + (size_t)b * CH * H * W;

    // ---- Load noise halo region 16 x 34 x 36 (zero outside image) ----
    for (int idx = t; idx < SN_FLOATS; idx += 256) {
        int c   = idx / (NH * NW);
        int rem = idx - c * (NH * NW);
        int nr  = rem / NW;
        int nc  = rem - nr * NW;
        int gy = ty0 - 5 + nr;
        int gx = tx0 - 5 + nc;
        float v = 0.0f;
        if ((unsigned)gy < (unsigned)H && (unsigned)gx < (unsigned)W)
            v = nb[(c * H + gy) * W + gx];
        sN[idx] = v;
    }
    __syncthreads();

    // thread map: r = corr row (0..27 for t<224; rows 26,27 clamped),
    //             g = col group, q0 = 4g (corr cols q0..q0+3)
    const int r  = t >> 3;
    const int g  = t & 7;
    const int q0 = g * 4;
    const int qc = min(q0, 24);          // clamp g7 smem addressing
    const int rc = min(r, 25);           // clamp rows 26,27
    const bool wk     = (t < 224);       // warp-uniform: warps 0..6 work
    const bool hstore = wk && (r < 26) && (g < 7);
    const bool vstore = (r >= 1) && (r <= 24) && (g <= 5);
    const int  rv = min(max(r, 1), 24);
    const float inv = 1.0f / 144.0f;

    // ---- center operand as packed f32x2 pairs, reused across all 81 offsets ----
    ull cenp[CH][2];
    if (wk) {
        #pragma unroll
        for (int c = 0; c < CH; c++) {
            float4 v = *(const float4*)&sN[(c * NH + rc + 4) * NW + qc + 4];
            cenp[c][0] = pk(v.x, v.y);
            cenp[c][1] = pk(v.z, v.w);
        }
    }

    #pragma unroll 1
    for (int di = 0; di < 9; di++) {
        ull a0[9], a1[9];
        #pragma unroll
        for (int dj = 0; dj < 9; dj++) { a0[dj] = 0ull; a1[dj] = 0ull; }

        if (wk) {
            // ---- mainloop: packed FFMA2, 3 LDS.128 + 18 fma.f32x2 per channel ----
            #pragma unroll
            for (int c = 0; c < CH; c++) {
                const float* row = &sN[(c * NH + rc + di) * NW + qc];
                float4 A = *(const float4*)(row);
                float4 B = *(const float4*)(row + 4);
                float4 C = *(const float4*)(row + 8);
                ull E0 = pk(A.x, A.y), E1 = pk(A.z, A.w);
                ull E2 = pk(B.x, B.y), E3 = pk(B.z, B.w);
                ull E4 = pk(C.x, C.y), E5 = pk(C.z, C.w);
                ull O0 = pk(A.y, A.z), O1 = pk(A.w, B.x);
                ull O2 = pk(B.y, B.z), O3 = pk(B.w, C.x);
                ull O4 = pk(C.y, C.z);
                ull m0 = cenp[c][0], m1 = cenp[c][1];
                ffma2(a0[0], m0, E0); ffma2(a0[1], m0, O0); ffma2(a0[2], m0, E1);
                ffma2(a0[3], m0, O1); ffma2(a0[4], m0, E2); ffma2(a0[5], m0, O2);
                ffma2(a0[6], m0, E3); ffma2(a0[7], m0, O3); ffma2(a0[8], m0, E4);
                ffma2(a1[0], m1, E1); ffma2(a1[1], m1, O1); ffma2(a1[2], m1, E2);
                ffma2(a1[3], m1, O2); ffma2(a1[4], m1, E3); ffma2(a1[5], m1, O3);
                ffma2(a1[6], m1, E4); ffma2(a1[7], m1, O4); ffma2(a1[8], m1, E5);
            }

            // ---- horizontal 3-sum in registers (shuffles); repack into a0/a1 ----
            #pragma unroll
            for (int dj = 0; dj < 9; dj++) {
                float c0, c1, c2, c3;
                upk(a0[dj], c0, c1); upk(a1[dj], c2, c3);
                float lft = __shfl_up_sync(FULL, c3, 1);    // neighbor's c3 = corr q0-1
                float rgt = __shfl_down_sync(FULL, c0, 1);  // neighbor's c0 = corr q0+4
                float h0 = lft + c0 + c1;
                float h1 = c0 + c1 + c2;
                float h2 = c1 + c2 + c3;
                float h3 = c2 + c3 + rgt;
                a0[dj] = pk(h0, h1); a1[dj] = pk(h2, h3);
            }
        }

        __syncthreads();   // previous iteration's vertical reads of sHS complete
        if (hstore) {
            #pragma unroll
            for (int dj = 0; dj < 9; dj++) {
                float h0, h1, h2, h3;
                upk(a0[dj], h0, h1); upk(a1[dj], h2, h3);
                *(float4*)&sHS[(dj * CR + r) * HSR + q0] = make_float4(h0, h1, h2, h3);
            }
        }
        __syncthreads();

        // ---- vertical 3-sum: own row in regs, 2 rows from smem, 3 shuffles ----
        if (wk) {
            #pragma unroll
            for (int dj = 0; dj < 9; dj++) {
                float h0, h1, h2, h3;
                upk(a0[dj], h0, h1); upk(a1[dj], h2, h3);
                float4 hm = *(const float4*)&sHS[(dj * CR + rv - 1) * HSR + qc];
                float4 hp = *(const float4*)&sHS[(dj * CR + rv + 1) * HSR + qc];
                float hmx = __shfl_down_sync(FULL, hm.x, 1);
                float hpx = __shfl_down_sync(FULL, hp.x, 1);
                float hox = __shfl_down_sync(FULL, h0, 1);
                if (vstore) {
                    float4 o;
                    o.x = (hm.y + h1 + hp.y) * inv;
                    o.y = (hm.z + h2 + hp.z) * inv;
                    o.z = (hm.w + h3 + hp.w) * inv;
                    o.w = (hmx + hox + hpx) * inv;
                    const int p = di * 9 + dj;
                    float* ob = out + (((size_t)b * 81 + p) * H + (ty0 + r - 1)) * W + tx0 + q0;
                    *(float4*)ob = o;
                }
            }
        }
    }
}

extern "C" void kernel_launch(void* const* d_in, const int* in_sizes, int n_in,
                              void* d_out, int out_size)
{
    const float* noise = (const float*)d_in[0];
    float* out = (float*)d_out;
    (void)in_sizes; (void)n_in; (void)out_size;

    cudaFuncSetAttribute(noisecorr_kernel,
                         cudaFuncAttributeMaxDynamicSharedMemorySize, SMEM_BYTES);

    dim3 grid(W / TILE, H / TILE, 8);   // 8 x 8 x 8 = 512 CTAs
    noisecorr_kernel<<<grid, 256, SMEM_BYTES>>>(noise, out);
}

// round 4
// speedup vs baseline: 1.2496x; 1.0014x over previous
#include <cuda_runtime.h>

using ull = unsigned long long;

namespace {
constexpr int TILE = 24;           // output tile edge; 192 % 24 == 0
constexpr int CR   = 26;           // corr rows (TILE + 2)
constexpr int NH   = 34, NW = 36;  // noise region rows/cols (stride NW)
constexpr int HSR  = 28;           // sHS row stride
constexpr int CH   = 16;
constexpr int H = 192, W = 192;
constexpr int SN_FLOATS  = CH * NH * NW;   // 19584
constexpr int SHS_FLOATS = 9 * CR * HSR;   // 6552
constexpr int SMEM_BYTES = (SN_FLOATS + SHS_FLOATS) * 4;  // 104544
constexpr unsigned FULL = 0xffffffffu;
}

__device__ __forceinline__ ull pk(float lo, float hi) {
    ull r; asm("mov.b64 %0, {%1,%2};" : "=l"(r) : "f"(lo), "f"(hi)); return r;
}
__device__ __forceinline__ void upk(ull v, float& lo, float& hi) {
    asm("mov.b64 {%0,%1}, %2;" : "=f"(lo), "=f"(hi) : "l"(v));
}
__device__ __forceinline__ void ffma2(ull& acc, ull m, ull s) {
    asm("fma.rn.f32x2 %0, %1, %2, %0;" : "+l"(acc) : "l"(m), "l"(s));
}

__global__ __launch_bounds__(256, 2)
void noisecorr_kernel(const float* __restrict__ noise, float* __restrict__ out)
{
    extern __shared__ float smem[];
    float* sN  = smem;               // [16][34][36]
    float* sHS = smem + SN_FLOATS;   // [9][26][28]

    const int t   = threadIdx.x;
    const int b   = blockIdx.z;
    const int ty0 = blockIdx.y * TILE;
    const int tx0 = blockIdx.x * TILE;
    const float* nb = noise + (size_t)b * CH * H * W;

    // ---- Load noise halo region 16 x 34 x 36 (zero outside image) ----
    for (int idx = t; idx < SN_FLOATS; idx += 256) {
        int c   = idx / (NH * NW);
        int rem = idx - c * (NH * NW);
        int nr  = rem / NW;
        int nc  = rem - nr * NW;
        int gy = ty0 - 5 + nr;
        int gx = tx0 - 5 + nc;
        float v = 0.0f;
        if ((unsigned)gy < (unsigned)H && (unsigned)gx < (unsigned)W)
            v = nb[(c * H + gy) * W + gx];
        sN[idx] = v;
    }
    __syncthreads();

    // thread map: r = corr row (0..27 for t<224; rows 26,27 clamped),
    //             g = col group, q0 = 4g (corr cols q0..q0+3)
    const int r  = t >> 3;
    const int g  = t & 7;
    const int q0 = g * 4;
    const int qc = min(q0, 24);          // clamp g7 smem addressing
    const int rc = min(r, 25);           // clamp rows 26,27
    const bool wk     = (t < 224);       // warp-uniform: warps 0..6 work
    const bool hstore = wk && (r < 26) && (g < 7);
    const bool vstore = (r >= 1) && (r <= 24) && (g <= 5);
    const int  rv = min(max(r, 1), 24);
    const float inv = 1.0f / 144.0f;

    // ---- center operand as packed f32x2 pairs, reused across all 81 offsets ----
    ull cenp[CH][2];
    if (wk) {
        #pragma unroll
        for (int c = 0; c < CH; c++) {
            float4 v = *(const float4*)&sN[(c * NH + rc + 4) * NW + qc + 4];
            cenp[c][0] = pk(v.x, v.y);
            cenp[c][1] = pk(v.z, v.w);
        }
    }

    #pragma unroll 1
    for (int di = 0; di < 9; di++) {
        ull a0[9], a1[9];
        #pragma unroll
        for (int dj = 0; dj < 9; dj++) { a0[dj] = 0ull; a1[dj] = 0ull; }

        if (wk) {
            // ---- mainloop: packed FFMA2, 3 LDS.128 + 18 fma.f32x2 per channel ----
            #pragma unroll
            for (int c = 0; c < CH; c++) {
                const float* row = &sN[(c * NH + rc + di) * NW + qc];
                float4 A = *(const float4*)(row);
                float4 B = *(const float4*)(row + 4);
                float4 C = *(const float4*)(row + 8);
                ull E0 = pk(A.x, A.y), E1 = pk(A.z, A.w);
                ull E2 = pk(B.x, B.y), E3 = pk(B.z, B.w);
                ull E4 = pk(C.x, C.y), E5 = pk(C.z, C.w);
                ull O0 = pk(A.y, A.z), O1 = pk(A.w, B.x);
                ull O2 = pk(B.y, B.z), O3 = pk(B.w, C.x);
                ull O4 = pk(C.y, C.z);
                ull m0 = cenp[c][0], m1 = cenp[c][1];
                ffma2(a0[0], m0, E0); ffma2(a0[1], m0, O0); ffma2(a0[2], m0, E1);
                ffma2(a0[3], m0, O1); ffma2(a0[4], m0, E2); ffma2(a0[5], m0, O2);
                ffma2(a0[6], m0, E3); ffma2(a0[7], m0, O3); ffma2(a0[8], m0, E4);
                ffma2(a1[0], m1, E1); ffma2(a1[1], m1, O1); ffma2(a1[2], m1, E2);
                ffma2(a1[3], m1, O2); ffma2(a1[4], m1, E3); ffma2(a1[5], m1, O3);
                ffma2(a1[6], m1, E4); ffma2(a1[7], m1, O4); ffma2(a1[8], m1, E5);
            }

            // ---- horizontal 3-sum in registers (shuffles); repack into a0/a1 ----
            #pragma unroll
            for (int dj = 0; dj < 9; dj++) {
                float c0, c1, c2, c3;
                upk(a0[dj], c0, c1); upk(a1[dj], c2, c3);
                float lft = __shfl_up_sync(FULL, c3, 1);    // neighbor's c3 = corr q0-1
                float rgt = __shfl_down_sync(FULL, c0, 1);  // neighbor's c0 = corr q0+4
                float h0 = lft + c0 + c1;
                float h1 = c0 + c1 + c2;
                float h2 = c1 + c2 + c3;
                float h3 = c2 + c3 + rgt;
                a0[dj] = pk(h0, h1); a1[dj] = pk(h2, h3);
            }
        }

        __syncthreads();   // previous iteration's vertical reads of sHS complete
        if (hstore) {
            #pragma unroll
            for (int dj = 0; dj < 9; dj++) {
                float h0, h1, h2, h3;
                upk(a0[dj], h0, h1); upk(a1[dj], h2, h3);
                *(float4*)&sHS[(dj * CR + r) * HSR + q0] = make_float4(h0, h1, h2, h3);
            }
        }
        __syncthreads();

        // ---- vertical 3-sum: own row in regs, 2 rows from smem, 3 shuffles ----
        if (wk) {
            #pragma unroll
            for (int dj = 0; dj < 9; dj++) {
                float h0, h1, h2, h3;
                upk(a0[dj], h0, h1); upk(a1[dj], h2, h3);
                float4 hm = *(const float4*)&sHS[(dj * CR + rv - 1) * HSR + qc];
                float4 hp = *(const float4*)&sHS[(dj * CR + rv + 1) * HSR + qc];
                float hmx = __shfl_down_sync(FULL, hm.x, 1);
                float hpx = __shfl_down_sync(FULL, hp.x, 1);
                float hox = __shfl_down_sync(FULL, h0, 1);
                if (vstore) {
                    float4 o;
                    o.x = (hm.y + h1 + hp.y) * inv;
                    o.y = (hm.z + h2 + hp.z) * inv;
                    o.z = (hm.w + h3 + hp.w) * inv;
                    o.w = (hmx + hox + hpx) * inv;
                    const int p = di * 9 + dj;
                    float* ob = out + (((size_t)b * 81 + p) * H + (ty0 + r - 1)) * W + tx0 + q0;
                    *(float4*)ob = o;
                }
            }
        }
    }
}

extern "C" void kernel_launch(void* const* d_in, const int* in_sizes, int n_in,
                              void* d_out, int out_size)
{
    const float* noise = (const float*)d_in[0];
    float* out = (float*)d_out;
    (void)in_sizes; (void)n_in; (void)out_size;

    cudaFuncSetAttribute(noisecorr_kernel,
                         cudaFuncAttributeMaxDynamicSharedMemorySize, SMEM_BYTES);

    dim3 grid(W / TILE, H / TILE, 8);   // 8 x 8 x 8 = 512 CTAs
    noisecorr_kernel<<<grid, 256, SMEM_BYTES>>>(noise, out);
}

// round 5
// speedup vs baseline: 1.3008x; 1.0410x over previous
#include <cuda_runtime.h>

using ull = unsigned long long;

namespace {
constexpr int TILE = 24;           // output tile edge; 192 % 24 == 0
constexpr int CR   = 26;           // corr rows (TILE + 2)
constexpr int NH   = 34, NW = 36;  // noise region rows/cols (stride NW)
constexpr int HSR  = 28;           // sHS row stride
constexpr int CH   = 16;
constexpr int H = 192, W = 192;
constexpr int SN_FLOATS  = CH * NH * NW;   // 19584
constexpr int SHS_FLOATS = 9 * CR * HSR;   // 6552
constexpr int SMEM_BYTES = (SN_FLOATS + SHS_FLOATS) * 4;  // 104544
constexpr unsigned FULL = 0xffffffffu;
constexpr int NT      = 224;               // 7 warps, no idle warp
constexpr int NHEAVY  = 22 * 8;            // heavy CTAs first (176)
constexpr int NBLOCKS = 64 * 8;            // 512
}

__device__ __forceinline__ ull pk(float lo, float hi) {
    ull r; asm("mov.b64 %0, {%1,%2};" : "=l"(r) : "f"(lo), "f"(hi)); return r;
}
__device__ __forceinline__ void upk(ull v, float& lo, float& hi) {
    asm("mov.b64 {%0,%1}, %2;" : "=f"(lo), "=f"(hi) : "l"(v));
}
__device__ __forceinline__ void ffma2(ull& acc, ull m, ull s) {
    asm("fma.rn.f32x2 %0, %1, %2, %0;" : "+l"(acc) : "l"(m), "l"(s));
}

__global__ __launch_bounds__(NT, 2)
void noisecorr_kernel(const float* __restrict__ noise, float* __restrict__ out)
{
    extern __shared__ float smem[];
    float* sN  = smem;               // [16][34][36]
    float* sHS = smem + SN_FLOATS;   // [9][26][28]

    const int t = threadIdx.x;

    // ---- heavy-first tile decode ----
    // heavy tiles (need di=0..3 for border strips): ty==0 | tx==0 | tx==7
    int b, tx, ty;
    bool heavy;
    {
        int bid = blockIdx.x;
        if (bid < NHEAVY) {
            heavy = true;
            b = bid / 22;
            int hi = bid - b * 22;
            if (hi < 8)       { ty = 0;       tx = hi;      }
            else if (hi < 15) { tx = 0;       ty = hi - 7;  }
            else              { tx = 7;       ty = hi - 14; }
        } else {
            heavy = false;
            int lb = bid - NHEAVY;
            b = lb / 42;
            int li = lb - b * 42;
            int row = li / 6;
            ty = 1 + row;
            tx = 1 + li - row * 6;
        }
    }
    const int ty0 = ty * TILE;
    const int tx0 = tx * TILE;
    const float* nb = noise + (size_t)b * CH * H * W;

    // ---- Load noise halo region 16 x 34 x 36 (zero outside image) ----
    for (int idx = t; idx < SN_FLOATS; idx += NT) {
        int c   = idx / (NH * NW);
        int rem = idx - c * (NH * NW);
        int nr  = rem / NW;
        int nc  = rem - nr * NW;
        int gy = ty0 - 5 + nr;
        int gx = tx0 - 5 + nc;
        float v = 0.0f;
        if ((unsigned)gy < (unsigned)H && (unsigned)gx < (unsigned)W)
            v = nb[(c * H + gy) * W + gx];
        sN[idx] = v;
    }
    __syncthreads();

    // thread map: r = corr row (0..27; rows 26,27 clamped), g = col group
    const int r  = t >> 3;
    const int g  = t & 7;
    const int q0 = g * 4;
    const int qc = min(q0, 24);          // clamp g7 smem addressing
    const int rc = min(r, 25);           // clamp rows 26,27
    const bool hstore = (r < 26) && (g < 7);
    const bool vstore = (r >= 1) && (r <= 24) && (g <= 5);
    const int  rv = min(max(r, 1), 24);
    const float inv = 1.0f / 144.0f;

    // ---- center operand as packed f32x2 pairs ----
    ull cenp[CH][2];
    #pragma unroll
    for (int c = 0; c < CH; c++) {
        float4 v = *(const float4*)&sN[(c * NH + rc + 4) * NW + qc + 4];
        cenp[c][0] = pk(v.x, v.y);
        cenp[c][1] = pk(v.z, v.w);
    }

    const int nIter = heavy ? 9 : 5;

    #pragma unroll 1
    for (int ii = 0; ii < nIter; ii++) {
        const int di = (ii < 5) ? (ii + 4) : (ii - 5);   // 4..8 first, then 0..3

        ull a0[9], a1[9];
        #pragma unroll
        for (int dj = 0; dj < 9; dj++) { a0[dj] = 0ull; a1[dj] = 0ull; }

        // ---- mainloop: packed FFMA2 ----
        {
            const float* rowp = &sN[(rc + di) * NW + qc];
            #pragma unroll
            for (int c = 0; c < CH; c++) {
                float4 A = *(const float4*)(rowp);
                float4 B = *(const float4*)(rowp + 4);
                float4 C = *(const float4*)(rowp + 8);
                rowp += NH * NW;
                ull E0 = pk(A.x, A.y), E1 = pk(A.z, A.w);
                ull E2 = pk(B.x, B.y), E3 = pk(B.z, B.w);
                ull E4 = pk(C.x, C.y), E5 = pk(C.z, C.w);
                ull O0 = pk(A.y, A.z), O1 = pk(A.w, B.x);
                ull O2 = pk(B.y, B.z), O3 = pk(B.w, C.x);
                ull O4 = pk(C.y, C.z);
                ull m0 = cenp[c][0], m1 = cenp[c][1];
                ffma2(a0[0], m0, E0); ffma2(a0[1], m0, O0); ffma2(a0[2], m0, E1);
                ffma2(a0[3], m0, O1); ffma2(a0[4], m0, E2); ffma2(a0[5], m0, O2);
                ffma2(a0[6], m0, E3); ffma2(a0[7], m0, O3); ffma2(a0[8], m0, E4);
                ffma2(a1[0], m1, E1); ffma2(a1[1], m1, O1); ffma2(a1[2], m1, E2);
                ffma2(a1[3], m1, O2); ffma2(a1[4], m1, E3); ffma2(a1[5], m1, O3);
                ffma2(a1[6], m1, E4); ffma2(a1[7], m1, O4); ffma2(a1[8], m1, E5);
            }
        }

        // ---- horizontal 3-sum in registers (shuffles) ----
        #pragma unroll
        for (int dj = 0; dj < 9; dj++) {
            float c0, c1, c2, c3;
            upk(a0[dj], c0, c1); upk(a1[dj], c2, c3);
            float lft = __shfl_up_sync(FULL, c3, 1);
            float rgt = __shfl_down_sync(FULL, c0, 1);
            float h0 = lft + c0 + c1;
            float h1 = c0 + c1 + c2;
            float h2 = c1 + c2 + c3;
            float h3 = c2 + c3 + rgt;
            a0[dj] = pk(h0, h1); a1[dj] = pk(h2, h3);
        }

        __syncthreads();   // previous iteration's vertical reads of sHS complete
        if (hstore) {
            #pragma unroll
            for (int dj = 0; dj < 9; dj++) {
                float h0, h1, h2, h3;
                upk(a0[dj], h0, h1); upk(a1[dj], h2, h3);
                *(float4*)&sHS[(dj * CR + r) * HSR + q0] = make_float4(h0, h1, h2, h3);
            }
        }
        __syncthreads();

        // ---- vertical 3-sum + direct store + mirror scatter ----
        {
            const int oy = ty0 + r - 1;
            #pragma unroll
            for (int dj = 0; dj < 9; dj++) {
                float h0, h1, h2, h3;
                upk(a0[dj], h0, h1); upk(a1[dj], h2, h3);
                float4 hm = *(const float4*)&sHS[(dj * CR + rv - 1) * HSR + qc];
                float4 hp = *(const float4*)&sHS[(dj * CR + rv + 1) * HSR + qc];
                float hmx = __shfl_down_sync(FULL, hm.x, 1);
                float hpx = __shfl_down_sync(FULL, hp.x, 1);
                float hox = __shfl_down_sync(FULL, h0, 1);
                if (vstore) {
                    float4 o;
                    o.x = (hm.y + h1 + hp.y) * inv;
                    o.y = (hm.z + h2 + hp.z) * inv;
                    o.z = (hm.w + h3 + hp.w) * inv;
                    o.w = (hmx + hox + hpx) * inv;
                    const int p = di * 9 + dj;
                    float* ob = out + (((size_t)b * 81 + p) * H + oy) * W + tx0 + q0;
                    *(float4*)ob = o;

                    // mirror: out_{80-p}(y + di-4, x + dj-4) = out_p(y, x), bitwise equal
                    if (di >= 5) {
                        const int ym = oy + (di - 4);
                        if (ym < H) {
                            const int pm = 80 - p;
                            const int xb = tx0 + q0 + (dj - 4);
                            float* om = out + (((size_t)b * 81 + pm) * H + ym) * W;
                            if ((unsigned)(xb + 0) < (unsigned)W) om[xb + 0] = o.x;
                            if ((unsigned)(xb + 1) < (unsigned)W) om[xb + 1] = o.y;
                            if ((unsigned)(xb + 2) < (unsigned)W) om[xb + 2] = o.z;
                            if ((unsigned)(xb + 3) < (unsigned)W) om[xb + 3] = o.w;
                        }
                    }
                }
            }
        }
    }
}

extern "C" void kernel_launch(void* const* d_in, const int* in_sizes, int n_in,
                              void* d_out, int out_size)
{
    const float* noise = (const float*)d_in[0];
    float* out = (float*)d_out;
    (void)in_sizes; (void)n_in; (void)out_size;

    cudaFuncSetAttribute(noisecorr_kernel,
                         cudaFuncAttributeMaxDynamicSharedMemorySize, SMEM_BYTES);

    noisecorr_kernel<<<NBLOCKS, NT, SMEM_BYTES>>>(noise, out);
}

// round 6
// speedup vs baseline: 1.4456x; 1.1113x over previous
#include <cuda_runtime.h>

using ull = unsigned long long;

namespace {
constexpr int TILE = 24;
constexpr int CR   = 26;           // main corr rows
constexpr int NH   = 34, NW = 36;  // main noise region
constexpr int HSR  = 28;
constexpr int CH   = 16;
constexpr int H = 192, W = 192;
constexpr int SN_FLOATS  = CH * NH * NW;   // 19584
constexpr int SHS_FLOATS = 9 * CR * HSR;   // 6552
constexpr int SMEM_BYTES = (SN_FLOATS + SHS_FLOATS) * 4;  // 104544 (max of 3 modes)
constexpr unsigned FULL = 0xffffffffu;
constexpr int NT = 224;

// top-strip geometry: rows 0..3, x-tiles of 96
constexpr int T_NH = 10, T_NW = 108, T_HSR = 100, T_CR = 6;
constexpr int T_SN = CH * T_NH * T_NW;       // 17280
// side-strip geometry: one 24-row band, left+right 4-col strips
constexpr int S_NH = 30, S_NW = 16, S_HSR = 8, S_CR = 26;
constexpr int S_SN = CH * S_NH * S_NW;       // 7680 per side
constexpr int S_HS = 9 * S_CR * S_HSR;       // 1872 per side

constexpr int N_MAIN = 512;                  // 8x8 tiles x 8 batch
constexpr int N_TOP  = 16;                   // 2 x-tiles x 8 batch
constexpr int N_SIDE = 64;                   // 8 y-bands x 8 batch
constexpr int NBLOCKS = N_MAIN + N_TOP + N_SIDE;  // 592
}

__device__ __forceinline__ ull pk(float lo, float hi) {
    ull r; asm("mov.b64 %0, {%1,%2};" : "=l"(r) : "f"(lo), "f"(hi)); return r;
}
__device__ __forceinline__ void upk(ull v, float& lo, float& hi) {
    asm("mov.b64 {%0,%1}, %2;" : "=f"(lo), "=f"(hi) : "l"(v));
}
__device__ __forceinline__ void ffma2(ull& acc, ull m, ull s) {
    asm("fma.rn.f32x2 %0, %1, %2, %0;" : "+l"(acc) : "l"(m), "l"(s));
}

// corr over 16 channels for 4 points x 9 dj, then horizontal 3-sum -> h[dj][0..3]
// base points at channel-0 shifted row (already offset by (rc+di)*rowstride + qc).
__device__ __forceinline__ void corr_hsum(const float* __restrict__ base, int chStride,
                                          const ull (&cenp)[CH][2], float (&h)[9][4])
{
    ull a0[9], a1[9];
    #pragma unroll
    for (int dj = 0; dj < 9; dj++) { a0[dj] = 0ull; a1[dj] = 0ull; }

    #pragma unroll
    for (int c = 0; c < CH; c++) {
        const float* row = base + c * chStride;
        float4 A = *(const float4*)(row);
        float4 B = *(const float4*)(row + 4);
        float4 C = *(const float4*)(row + 8);
        ull E0 = pk(A.x, A.y), E1 = pk(A.z, A.w);
        ull E2 = pk(B.x, B.y), E3 = pk(B.z, B.w);
        ull E4 = pk(C.x, C.y), E5 = pk(C.z, C.w);
        ull O0 = pk(A.y, A.z), O1 = pk(A.w, B.x);
        ull O2 = pk(B.y, B.z), O3 = pk(B.w, C.x);
        ull O4 = pk(C.y, C.z);
        ull m0 = cenp[c][0], m1 = cenp[c][1];
        ffma2(a0[0], m0, E0); ffma2(a0[1], m0, O0); ffma2(a0[2], m0, E1);
        ffma2(a0[3], m0, O1); ffma2(a0[4], m0, E2); ffma2(a0[5], m0, O2);
        ffma2(a0[6], m0, E3); ffma2(a0[7], m0, O3); ffma2(a0[8], m0, E4);
        ffma2(a1[0], m1, E1); ffma2(a1[1], m1, O1); ffma2(a1[2], m1, E2);
        ffma2(a1[3], m1, O2); ffma2(a1[4], m1, E3); ffma2(a1[5], m1, O3);
        ffma2(a1[6], m1, E4); ffma2(a1[7], m1, O4); ffma2(a1[8], m1, E5);
    }

    #pragma unroll
    for (int dj = 0; dj < 9; dj++) {
        float c0, c1, c2, c3;
        upk(a0[dj], c0, c1); upk(a1[dj], c2, c3);
        float lft = __shfl_up_sync(FULL, c3, 1);
        float rgt = __shfl_down_sync(FULL, c0, 1);
        h[dj][0] = lft + c0 + c1;
        h[dj][1] = c0 + c1 + c2;
        h[dj][2] = c1 + c2 + c3;
        h[dj][3] = c2 + c3 + rgt;
    }
}

__global__ __launch_bounds__(NT, 2)
void noisecorr_kernel(const float* __restrict__ noise, float* __restrict__ out)
{
    extern __shared__ float smem[];
    const int t   = threadIdx.x;
    const int bid = blockIdx.x;
    const float inv = 1.0f / 144.0f;

    if (bid < N_MAIN) {
        // ================= MAIN: di 4..8 direct + mirror scatter =================
        float* sN  = smem;
        float* sHS = smem + SN_FLOATS;
        const int b  = bid >> 6;
        const int ty = (bid >> 3) & 7;
        const int tx = bid & 7;
        const int ty0 = ty * TILE, tx0 = tx * TILE;
        const float* nb = noise + (size_t)b * CH * H * W;

        for (int idx = t; idx < SN_FLOATS; idx += NT) {
            int c   = idx / (NH * NW);
            int rem = idx - c * (NH * NW);
            int nr  = rem / NW;
            int nc  = rem - nr * NW;
            int gy = ty0 - 5 + nr, gx = tx0 - 5 + nc;
            float v = 0.0f;
            if ((unsigned)gy < (unsigned)H && (unsigned)gx < (unsigned)W)
                v = nb[(c * H + gy) * W + gx];
            sN[idx] = v;
        }
        __syncthreads();

        const int r  = t >> 3;
        const int g  = t & 7;
        const int q0 = g * 4;
        const int qc = min(q0, 24);
        const int rc = min(r, 25);
        const bool hstore = (r < 26) && (g < 7);
        const bool vstore = (r >= 1) && (r <= 24) && (g <= 5);
        const int  rv = min(max(r, 1), 24);
        const bool xs = (tx >= 1) && (tx <= 6);   // scatter x in-bounds for interior tiles
        const bool ys = (ty <= 6);                // scatter y in-bounds except bottom row

        ull cenp[CH][2];
        #pragma unroll
        for (int c = 0; c < CH; c++) {
            float4 v = *(const float4*)&sN[(c * NH + rc + 4) * NW + qc + 4];
            cenp[c][0] = pk(v.x, v.y);
            cenp[c][1] = pk(v.z, v.w);
        }

        #pragma unroll 1
        for (int ii = 0; ii < 5; ii++) {
            const int di = ii + 4;
            float h[9][4];
            corr_hsum(&sN[(rc + di) * NW + qc], NH * NW, cenp, h);

            __syncthreads();
            if (hstore) {
                #pragma unroll
                for (int dj = 0; dj < 9; dj++)
                    *(float4*)&sHS[(dj * CR + r) * HSR + q0] =
                        make_float4(h[dj][0], h[dj][1], h[dj][2], h[dj][3]);
            }
            __syncthreads();

            const int oy = ty0 + r - 1;
            #pragma unroll
            for (int dj = 0; dj < 9; dj++) {
                float4 hm = *(const float4*)&sHS[(dj * CR + rv - 1) * HSR + qc];
                float4 hp = *(const float4*)&sHS[(dj * CR + rv + 1) * HSR + qc];
                float hmx = __shfl_down_sync(FULL, hm.x, 1);
                float hpx = __shfl_down_sync(FULL, hp.x, 1);
                float hox = __shfl_down_sync(FULL, h[dj][0], 1);
                if (vstore) {
                    float4 o;
                    o.x = (hm.y + h[dj][1] + hp.y) * inv;
                    o.y = (hm.z + h[dj][2] + hp.z) * inv;
                    o.z = (hm.w + h[dj][3] + hp.w) * inv;
                    o.w = (hmx + hox + hpx) * inv;
                    const int p = di * 9 + dj;
                    float* ob = out + (((size_t)b * 81 + p) * H + oy) * W + tx0 + q0;
                    *(float4*)ob = o;

                    if (di >= 5) {   // mirror: out_{80-p}(y+di-4, x+dj-4), bitwise equal
                        const int ym = oy + (di - 4);
                        if (ys || ym < H) {
                            const int pm = 80 - p;
                            const int xb = tx0 + q0 + (dj - 4);
                            float* om = out + (((size_t)b * 81 + pm) * H + ym) * W;
                            if (xs) {
                                om[xb + 0] = o.x; om[xb + 1] = o.y;
                                om[xb + 2] = o.z; om[xb + 3] = o.w;
                            } else {
                                if ((unsigned)(xb + 0) < (unsigned)W) om[xb + 0] = o.x;
                                if ((unsigned)(xb + 1) < (unsigned)W) om[xb + 1] = o.y;
                                if ((unsigned)(xb + 2) < (unsigned)W) om[xb + 2] = o.z;
                                if ((unsigned)(xb + 3) < (unsigned)W) om[xb + 3] = o.w;
                            }
                        }
                    }
                }
            }
        }
    } else if (bid < N_MAIN + N_TOP) {
        // ================= TOP STRIP: planes di 0..3, rows 0..3, full width ======
        float* sN  = smem;
        float* sHS = smem + T_SN;
        const int idx0 = bid - N_MAIN;
        const int b    = idx0 >> 1;
        const int tx0  = (idx0 & 1) * 96;
        const float* nb = noise + (size_t)b * CH * H * W;

        for (int idx = t; idx < T_SN; idx += NT) {
            int c   = idx / (T_NH * T_NW);
            int rem = idx - c * (T_NH * T_NW);
            int nr  = rem / T_NW;
            int nc  = rem - nr * T_NW;
            int gy = nr - 5, gx = tx0 - 5 + nc;
            float v = 0.0f;
            if ((unsigned)gy < (unsigned)H && (unsigned)gx < (unsigned)W)
                v = nb[(c * H + gy) * W + gx];
            sN[idx] = v;
        }
        __syncthreads();

        const int r  = t >> 5;          // warp = one corr row (0..6)
        const int g  = t & 31;
        const int q0 = g * 4;
        const int qc = min(q0, 96);
        const int rc = min(r, 5);
        const bool hstore = (r < 6) && (g < 25);
        const bool vstore = (r >= 1) && (r <= 4) && (g <= 23);
        const int  rv = min(max(r, 1), 4);

        ull cenp[CH][2];
        #pragma unroll
        for (int c = 0; c < CH; c++) {
            float4 v = *(const float4*)&sN[(c * T_NH + rc + 4) * T_NW + qc + 4];
            cenp[c][0] = pk(v.x, v.y);
            cenp[c][1] = pk(v.z, v.w);
        }

        #pragma unroll 1
        for (int di = 0; di < 4; di++) {
            float h[9][4];
            corr_hsum(&sN[(rc + di) * T_NW + qc], T_NH * T_NW, cenp, h);

            __syncthreads();
            if (hstore) {
                #pragma unroll
                for (int dj = 0; dj < 9; dj++)
                    *(float4*)&sHS[(dj * T_CR + r) * T_HSR + q0] =
                        make_float4(h[dj][0], h[dj][1], h[dj][2], h[dj][3]);
            }
            __syncthreads();

            const int oy = r - 1;
            #pragma unroll
            for (int dj = 0; dj < 9; dj++) {
                float4 hm = *(const float4*)&sHS[(dj * T_CR + rv - 1) * T_HSR + qc];
                float4 hp = *(const float4*)&sHS[(dj * T_CR + rv + 1) * T_HSR + qc];
                float hmx = __shfl_down_sync(FULL, hm.x, 1);
                float hpx = __shfl_down_sync(FULL, hp.x, 1);
                float hox = __shfl_down_sync(FULL, h[dj][0], 1);
                if (vstore) {
                    float4 o;
                    o.x = (hm.y + h[dj][1] + hp.y) * inv;
                    o.y = (hm.z + h[dj][2] + hp.z) * inv;
                    o.z = (hm.w + h[dj][3] + hp.w) * inv;
                    o.w = (hmx + hox + hpx) * inv;
                    const int p = di * 9 + dj;
                    float* ob = out + (((size_t)b * 81 + p) * H + oy) * W + tx0 + q0;
                    *(float4*)ob = o;
                }
            }
        }
    } else {
        // ================= SIDE STRIPS: planes di 0..3, cols 0..3 & 188..191 =====
        float* sNL  = smem;                    // [16][30][16]
        float* sNR  = smem + S_SN;
        float* sHSL = smem + 2 * S_SN;         // [9][26][8]
        float* sHSR = smem + 2 * S_SN + S_HS;
        const int idx0 = bid - N_MAIN - N_TOP;
        const int b = idx0 >> 3;
        const int k = idx0 & 7;
        const int y0 = (k == 7) ? 168 : 4 + 24 * k;   // overlap rows write identical values
        const float* nb = noise + (size_t)b * CH * H * W;

        for (int idx = t; idx < 2 * S_SN; idx += NT) {
            int side = idx / S_SN;
            int w    = idx - side * S_SN;
            int c    = w / (S_NH * S_NW);
            int rem  = w - c * (S_NH * S_NW);
            int nr   = rem >> 4;
            int nc   = rem & 15;
            int gy = y0 - 5 + nr;
            int gx = (side ? 183 : -5) + nc;
            float v = 0.0f;
            if ((unsigned)gy < (unsigned)H && (unsigned)gx < (unsigned)W)
                v = nb[(c * H + gy) * W + gx];
            smem[side ? (S_SN + w) : w] = v;
        }
        __syncthreads();

        const bool active = (t < 128);        // warps 0..3 (warp-uniform)
        const int r  = t >> 2;                // 0..31 in active warps
        const int g  = t & 3;                 // 0,1 = left; 2,3 = right
        const int gg = g & 1;
        const int sd = g >> 1;
        const int q0 = gg * 4;
        const int rc = min(r, 25);
        const bool hstore = active && (r < 26);
        const bool vstore = active && (gg == 0) && (r >= 1) && (r <= 24);
        const int  rv = min(max(r, 1), 24);
        float* sNs  = sd ? sNR : sNL;
        float* sHSs = sd ? sHSR : sHSL;
        const int ox = sd ? 188 : 0;

        ull cenp[CH][2];
        if (active) {
            #pragma unroll
            for (int c = 0; c < CH; c++) {
                float4 v = *(const float4*)&sNs[(c * S_NH + rc + 4) * S_NW + q0 + 4];
                cenp[c][0] = pk(v.x, v.y);
                cenp[c][1] = pk(v.z, v.w);
            }
        }

        #pragma unroll 1
        for (int di = 0; di < 4; di++) {
            float h[9][4];
            if (active)
                corr_hsum(&sNs[(rc + di) * S_NW + q0], S_NH * S_NW, cenp, h);

            __syncthreads();
            if (hstore) {
                #pragma unroll
                for (int dj = 0; dj < 9; dj++)
                    *(float4*)&sHSs[(dj * S_CR + r) * S_HSR + q0] =
                        make_float4(h[dj][0], h[dj][1], h[dj][2], h[dj][3]);
            }
            __syncthreads();

            if (active) {
                const int oy = y0 + r - 1;
                #pragma unroll
                for (int dj = 0; dj < 9; dj++) {
                    float4 hm = *(const float4*)&sHSs[(dj * S_CR + rv - 1) * S_HSR + q0];
                    float4 hp = *(const float4*)&sHSs[(dj * S_CR + rv + 1) * S_HSR + q0];
                    float hmx = __shfl_down_sync(FULL, hm.x, 1);
                    float hpx = __shfl_down_sync(FULL, hp.x, 1);
                    float hox = __shfl_down_sync(FULL, h[dj][0], 1);
                    if (vstore) {
                        float4 o;
                        o.x = (hm.y + h[dj][1] + hp.y) * inv;
                        o.y = (hm.z + h[dj][2] + hp.z) * inv;
                        o.z = (hm.w + h[dj][3] + hp.w) * inv;
                        o.w = (hmx + hox + hpx) * inv;
                        const int p = di * 9 + dj;
                        float* ob = out + (((size_t)b * 81 + p) * H + oy) * W + ox;
                        *(float4*)ob = o;
                    }
                }
            }
        }
    }
}

extern "C" void kernel_launch(void* const* d_in, const int* in_sizes, int n_in,
                              void* d_out, int out_size)
{
    const float* noise = (const float*)d_in[0];
    float* out = (float*)d_out;
    (void)in_sizes; (void)n_in; (void)out_size;

    cudaFuncSetAttribute(noisecorr_kernel,
                         cudaFuncAttributeMaxDynamicSharedMemorySize, SMEM_BYTES);

    noisecorr_kernel<<<NBLOCKS, NT, SMEM_BYTES>>>(noise, out);
}

// round 7
// speedup vs baseline: 1.5358x; 1.0624x over previous
#include <cuda_runtime.h>

using ull = unsigned long long;

namespace {
constexpr int CH = 16;
constexpr int H = 192, W = 192;
constexpr unsigned FULL = 0xffffffffu;
constexpr int NT = 256;

// main tile: 28 rows x 24 cols output; corr 30x26; noise rows 34 (R..R+4 only), cols 36
constexpr int NH = 34, NW = 36;
constexpr int CRH = 30;            // corr rows stored in sHS
constexpr int HSR = 28;
constexpr int SN_FLOATS  = CH * NH * NW;    // 19584
constexpr int SHS_FLOATS = 9 * CRH * HSR;   // 7560
constexpr int SMEM_BYTES = (SN_FLOATS + SHS_FLOATS) * 4;  // 108576

// top-strip geometry: rows 0..3, x-tiles of 96
constexpr int T_NH = 10, T_NW = 108, T_HSR = 100, T_CR = 6;
constexpr int T_SN = CH * T_NH * T_NW;       // 17280
// side-strip geometry: one 24-row band, left+right 4-col strips
constexpr int S_NH = 30, S_NW = 16, S_HSR = 8, S_CR = 26;
constexpr int S_SN = CH * S_NH * S_NW;       // 7680 per side
constexpr int S_HS = 9 * S_CR * S_HSR;       // 1872 per side

constexpr int N_MAIN = 448;                  // 7 y-bands x 8 x-tiles x 8 batch
constexpr int N_TOP  = 16;
constexpr int N_SIDE = 64;
constexpr int NBLOCKS = N_MAIN + N_TOP + N_SIDE;  // 528
}

__device__ __forceinline__ ull pk(float lo, float hi) {
    ull r; asm("mov.b64 %0, {%1,%2};" : "=l"(r) : "f"(lo), "f"(hi)); return r;
}
__device__ __forceinline__ void upk(ull v, float& lo, float& hi) {
    asm("mov.b64 {%0,%1}, %2;" : "=f"(lo), "=f"(hi) : "l"(v));
}
__device__ __forceinline__ void ffma2(ull& acc, ull m, ull s) {
    asm("fma.rn.f32x2 %0, %1, %2, %0;" : "+l"(acc) : "l"(m), "l"(s));
}

// corr over 16 channels for 4 points x 9 dj, then horizontal 3-sum -> h[dj][0..3]
__device__ __forceinline__ void corr_hsum(const float* __restrict__ base, int chStride,
                                          const ull (&cenp)[CH][2], float (&h)[9][4])
{
    ull a0[9], a1[9];
    #pragma unroll
    for (int dj = 0; dj < 9; dj++) { a0[dj] = 0ull; a1[dj] = 0ull; }

    #pragma unroll
    for (int c = 0; c < CH; c++) {
        const float* row = base + c * chStride;
        float4 A = *(const float4*)(row);
        float4 B = *(const float4*)(row + 4);
        float4 C = *(const float4*)(row + 8);
        ull E0 = pk(A.x, A.y), E1 = pk(A.z, A.w);
        ull E2 = pk(B.x, B.y), E3 = pk(B.z, B.w);
        ull E4 = pk(C.x, C.y), E5 = pk(C.z, C.w);
        ull O0 = pk(A.y, A.z), O1 = pk(A.w, B.x);
        ull O2 = pk(B.y, B.z), O3 = pk(B.w, C.x);
        ull O4 = pk(C.y, C.z);
        ull m0 = cenp[c][0], m1 = cenp[c][1];
        ffma2(a0[0], m0, E0); ffma2(a0[1], m0, O0); ffma2(a0[2], m0, E1);
        ffma2(a0[3], m0, O1); ffma2(a0[4], m0, E2); ffma2(a0[5], m0, O2);
        ffma2(a0[6], m0, E3); ffma2(a0[7], m0, O3); ffma2(a0[8], m0, E4);
        ffma2(a1[0], m1, E1); ffma2(a1[1], m1, O1); ffma2(a1[2], m1, E2);
        ffma2(a1[3], m1, O2); ffma2(a1[4], m1, E3); ffma2(a1[5], m1, O3);
        ffma2(a1[6], m1, E4); ffma2(a1[7], m1, O4); ffma2(a1[8], m1, E5);
    }

    #pragma unroll
    for (int dj = 0; dj < 9; dj++) {
        float c0, c1, c2, c3;
        upk(a0[dj], c0, c1); upk(a1[dj], c2, c3);
        float lft = __shfl_up_sync(FULL, c3, 1);
        float rgt = __shfl_down_sync(FULL, c0, 1);
        h[dj][0] = lft + c0 + c1;
        h[dj][1] = c0 + c1 + c2;
        h[dj][2] = c1 + c2 + c3;
        h[dj][3] = c2 + c3 + rgt;
    }
}

__global__ __launch_bounds__(NT, 2)
void noisecorr_kernel(const float* __restrict__ noise, float* __restrict__ out)
{
    extern __shared__ float smem[];
    const int t   = threadIdx.x;
    const int bid = blockIdx.x;
    const float inv = 1.0f / 144.0f;

    if (bid < N_MAIN) {
        // ================= MAIN: di 4..8 direct + mirror scatter =================
        float* sN  = smem;                  // [16][34][36], row 0 = global y0-1
        float* sHS = smem + SN_FLOATS;      // [9][30][28]
        const int b   = bid / 56;
        const int rem = bid - b * 56;
        const int ty  = rem >> 3;
        const int tx  = rem & 7;
        const int y0  = (ty < 6) ? ty * 28 : 164;   // band 6 overlaps band 5 (benign)
        const int tx0 = tx * 24;
        const float* nb = noise + (size_t)b * CH * H * W;

        for (int idx = t; idx < SN_FLOATS; idx += NT) {
            int c   = idx / (NH * NW);
            int r2  = idx - c * (NH * NW);
            int nr  = r2 / NW;
            int nc  = r2 - nr * NW;
            int gy = y0 - 1 + nr, gx = tx0 - 5 + nc;
            float v = 0.0f;
            if ((unsigned)gy < (unsigned)H && (unsigned)gx < (unsigned)W)
                v = nb[(c * H + gy) * W + gx];
            sN[idx] = v;
        }
        __syncthreads();

        const int r  = t >> 3;               // 0..31; rows 30,31 clamped
        const int g  = t & 7;
        const int q0 = g * 4;
        const int qc = min(q0, 24);
        const int rc = min(r, 29);
        const bool hstore = (r < 30) && (g < 7);
        const bool vstore = (r >= 1) && (r <= 28) && (g <= 5);
        const int  rv = min(max(r, 1), 28);
        const bool xs = (tx >= 1) && (tx <= 6);
        const bool ys = (ty != 6);

        ull cenp[CH][2];
        #pragma unroll
        for (int c = 0; c < CH; c++) {
            float4 v = *(const float4*)&sN[(c * NH + rc) * NW + qc + 4];
            cenp[c][0] = pk(v.x, v.y);
            cenp[c][1] = pk(v.z, v.w);
        }

        #pragma unroll 1
        for (int k = 0; k < 5; k++) {        // di = k + 4
            float h[9][4];
            corr_hsum(&sN[(rc + k) * NW + qc], NH * NW, cenp, h);

            __syncthreads();
            if (hstore) {
                #pragma unroll
                for (int dj = 0; dj < 9; dj++)
                    *(float4*)&sHS[(dj * CRH + r) * HSR + q0] =
                        make_float4(h[dj][0], h[dj][1], h[dj][2], h[dj][3]);
            }
            __syncthreads();

            const int oy = y0 + r - 1;
            #pragma unroll
            for (int dj = 0; dj < 9; dj++) {
                float4 hm = *(const float4*)&sHS[(dj * CRH + rv - 1) * HSR + qc];
                float4 hp = *(const float4*)&sHS[(dj * CRH + rv + 1) * HSR + qc];
                float hmx = __shfl_down_sync(FULL, hm.x, 1);
                float hpx = __shfl_down_sync(FULL, hp.x, 1);
                float hox = __shfl_down_sync(FULL, h[dj][0], 1);
                if (vstore) {
                    float4 o;
                    o.x = (hm.y + h[dj][1] + hp.y) * inv;
                    o.y = (hm.z + h[dj][2] + hp.z) * inv;
                    o.z = (hm.w + h[dj][3] + hp.w) * inv;
                    o.w = (hmx + hox + hpx) * inv;
                    const int p = (k + 4) * 9 + dj;
                    float* ob = out + (((size_t)b * 81 + p) * H + oy) * W + tx0 + q0;
                    *(float4*)ob = o;

                    if (k >= 1) {   // mirror: out_{80-p}(y+k, x+dj-4), bitwise equal
                        const int ym = oy + k;
                        if (ys || ym < H) {
                            const int pm = 80 - p;
                            const int xb = tx0 + q0 + (dj - 4);
                            float* om = out + (((size_t)b * 81 + pm) * H + ym) * W;
                            if (xs) {
                                if ((dj & 1) == 0) {   // xb even -> 2x STG.64
                                    *(float2*)&om[xb]     = make_float2(o.x, o.y);
                                    *(float2*)&om[xb + 2] = make_float2(o.z, o.w);
                                } else {               // xb odd
                                    om[xb] = o.x;
                                    *(float2*)&om[xb + 1] = make_float2(o.y, o.z);
                                    om[xb + 3] = o.w;
                                }
                            } else {
                                if ((unsigned)(xb + 0) < (unsigned)W) om[xb + 0] = o.x;
                                if ((unsigned)(xb + 1) < (unsigned)W) om[xb + 1] = o.y;
                                if ((unsigned)(xb + 2) < (unsigned)W) om[xb + 2] = o.z;
                                if ((unsigned)(xb + 3) < (unsigned)W) om[xb + 3] = o.w;
                            }
                        }
                    }
                }
            }
        }
    } else if (bid < N_MAIN + N_TOP) {
        // ================= TOP STRIP: planes di 0..3, rows 0..3, full width ======
        float* sN  = smem;
        float* sHS = smem + T_SN;
        const int idx0 = bid - N_MAIN;
        const int b    = idx0 >> 1;
        const int tx0  = (idx0 & 1) * 96;
        const float* nb = noise + (size_t)b * CH * H * W;

        for (int idx = t; idx < T_SN; idx += NT) {
            int c   = idx / (T_NH * T_NW);
            int r2  = idx - c * (T_NH * T_NW);
            int nr  = r2 / T_NW;
            int nc  = r2 - nr * T_NW;
            int gy = nr - 5, gx = tx0 - 5 + nc;
            float v = 0.0f;
            if ((unsigned)gy < (unsigned)H && (unsigned)gx < (unsigned)W)
                v = nb[(c * H + gy) * W + gx];
            sN[idx] = v;
        }
        __syncthreads();

        const int r  = t >> 5;          // 0..7; rows 6,7 clamped/idle
        const int g  = t & 31;
        const int q0 = g * 4;
        const int qc = min(q0, 96);
        const int rc = min(r, 5);
        const bool hstore = (r < 6) && (g < 25);
        const bool vstore = (r >= 1) && (r <= 4) && (g <= 23);
        const int  rv = min(max(r, 1), 4);

        ull cenp[CH][2];
        #pragma unroll
        for (int c = 0; c < CH; c++) {
            float4 v = *(const float4*)&sN[(c * T_NH + rc + 4) * T_NW + qc + 4];
            cenp[c][0] = pk(v.x, v.y);
            cenp[c][1] = pk(v.z, v.w);
        }

        #pragma unroll 1
        for (int di = 0; di < 4; di++) {
            float h[9][4];
            corr_hsum(&sN[(rc + di) * T_NW + qc], T_NH * T_NW, cenp, h);

            __syncthreads();
            if (hstore) {
                #pragma unroll
                for (int dj = 0; dj < 9; dj++)
                    *(float4*)&sHS[(dj * T_CR + r) * T_HSR + q0] =
                        make_float4(h[dj][0], h[dj][1], h[dj][2], h[dj][3]);
            }
            __syncthreads();

            const int oy = r - 1;
            #pragma unroll
            for (int dj = 0; dj < 9; dj++) {
                float4 hm = *(const float4*)&sHS[(dj * T_CR + rv - 1) * T_HSR + qc];
                float4 hp = *(const float4*)&sHS[(dj * T_CR + rv + 1) * T_HSR + qc];
                float hmx = __shfl_down_sync(FULL, hm.x, 1);
                float hpx = __shfl_down_sync(FULL, hp.x, 1);
                float hox = __shfl_down_sync(FULL, h[dj][0], 1);
                if (vstore) {
                    float4 o;
                    o.x = (hm.y + h[dj][1] + hp.y) * inv;
                    o.y = (hm.z + h[dj][2] + hp.z) * inv;
                    o.z = (hm.w + h[dj][3] + hp.w) * inv;
                    o.w = (hmx + hox + hpx) * inv;
                    const int p = di * 9 + dj;
                    float* ob = out + (((size_t)b * 81 + p) * H + oy) * W + tx0 + q0;
                    *(float4*)ob = o;
                }
            }
        }
    } else {
        // ================= SIDE STRIPS: planes di 0..3, cols 0..3 & 188..191 =====
        float* sNL  = smem;
        float* sNR  = smem + S_SN;
        float* sHSL = smem + 2 * S_SN;
        float* sHSR = smem + 2 * S_SN + S_HS;
        const int idx0 = bid - N_MAIN - N_TOP;
        const int b = idx0 >> 3;
        const int k = idx0 & 7;
        const int y0 = (k == 7) ? 168 : 4 + 24 * k;
        const float* nb = noise + (size_t)b * CH * H * W;

        for (int idx = t; idx < 2 * S_SN; idx += NT) {
            int side = idx / S_SN;
            int w    = idx - side * S_SN;
            int c    = w / (S_NH * S_NW);
            int r2   = w - c * (S_NH * S_NW);
            int nr   = r2 >> 4;
            int nc   = r2 & 15;
            int gy = y0 - 5 + nr;
            int gx = (side ? 183 : -5) + nc;
            float v = 0.0f;
            if ((unsigned)gy < (unsigned)H && (unsigned)gx < (unsigned)W)
                v = nb[(c * H + gy) * W + gx];
            smem[side ? (S_SN + w) : w] = v;
        }
        __syncthreads();

        const bool active = (t < 128);
        const int r  = t >> 2;
        const int g  = t & 3;
        const int gg = g & 1;
        const int sd = g >> 1;
        const int q0 = gg * 4;
        const int rc = min(r, 25);
        const bool hstore = active && (r < 26);
        const bool vstore = active && (gg == 0) && (r >= 1) && (r <= 24);
        const int  rv = min(max(r, 1), 24);
        float* sNs  = sd ? sNR : sNL;
        float* sHSs = sd ? sHSR : sHSL;
        const int ox = sd ? 188 : 0;

        ull cenp[CH][2];
        if (active) {
            #pragma unroll
            for (int c = 0; c < CH; c++) {
                float4 v = *(const float4*)&sNs[(c * S_NH + rc + 4) * S_NW + q0 + 4];
                cenp[c][0] = pk(v.x, v.y);
                cenp[c][1] = pk(v.z, v.w);
            }
        }

        #pragma unroll 1
        for (int di = 0; di < 4; di++) {
            float h[9][4];
            if (active)
                corr_hsum(&sNs[(rc + di) * S_NW + q0], S_NH * S_NW, cenp, h);

            __syncthreads();
            if (hstore) {
                #pragma unroll
                for (int dj = 0; dj < 9; dj++)
                    *(float4*)&sHSs[(dj * S_CR + r) * S_HSR + q0] =
                        make_float4(h[dj][0], h[dj][1], h[dj][2], h[dj][3]);
            }
            __syncthreads();

            if (active) {
                const int oy = y0 + r - 1;
                #pragma unroll
                for (int dj = 0; dj < 9; dj++) {
                    float4 hm = *(const float4*)&sHSs[(dj * S_CR + rv - 1) * S_HSR + q0];
                    float4 hp = *(const float4*)&sHSs[(dj * S_CR + rv + 1) * S_HSR + q0];
                    float hmx = __shfl_down_sync(FULL, hm.x, 1);
                    float hpx = __shfl_down_sync(FULL, hp.x, 1);
                    float hox = __shfl_down_sync(FULL, h[dj][0], 1);
                    if (vstore) {
                        float4 o;
                        o.x = (hm.y + h[dj][1] + hp.y) * inv;
                        o.y = (hm.z + h[dj][2] + hp.z) * inv;
                        o.z = (hm.w + h[dj][3] + hp.w) * inv;
                        o.w = (hmx + hox + hpx) * inv;
                        const int p = di * 9 + dj;
                        float* ob = out + (((size_t)b * 81 + p) * H + oy) * W + ox;
                        *(float4*)ob = o;
                    }
                }
            }
        }
    }
}

extern "C" void kernel_launch(void* const* d_in, const int* in_sizes, int n_in,
                              void* d_out, int out_size)
{
    const float* noise = (const float*)d_in[0];
    float* out = (float*)d_out;
    (void)in_sizes; (void)n_in; (void)out_size;

    cudaFuncSetAttribute(noisecorr_kernel,
                         cudaFuncAttributeMaxDynamicSharedMemorySize, SMEM_BYTES);

    noisecorr_kernel<<<NBLOCKS, NT, SMEM_BYTES>>>(noise, out);
}